// round 2
// baseline (speedup 1.0000x reference)
#include <cuda_runtime.h>

#define BB   256   // batch
#define TT   512   // seq len
#define DD   50    // char dim
#define HH   128   // per-direction hidden
#define G4   512   // 4*HH
#define HID  256   // output hidden

// Scratch (device globals: allocation-free per harness rules)
__device__ float g_xg[2][TT][BB][G4];      // precomputed input gates, 512 MB
__device__ float g_h[2][2][BB][HH];        // double-buffered h state [parity][dir][b][k]
__device__ float g_c[2][BB][HH];           // c state [dir][b][k]

__device__ __forceinline__ float sigf(float x) {
    return 1.0f / (1.0f + __expf(-x));
}
__device__ __forceinline__ float tanh_fast(float x) {
    // 2*sigmoid(2x)-1 ; __expf handles overflow to +-1 correctly via inf
    return 2.0f / (1.0f + __expf(-2.0f * x)) - 1.0f;
}

// ---------------------------------------------------------------------------
// Init: zero h/c state, set running-max output to -inf-ish
// grid 256 x 256 threads = 65536
// ---------------------------------------------------------------------------
__global__ void init_kernel(float* __restrict__ out) {
    int i = blockIdx.x * blockDim.x + threadIdx.x;   // 0..65535
    out[i] = -3.0e38f;
    float* h = &g_h[0][0][0][0];
    h[i]         = 0.0f;   // parity 0
    h[i + 65536] = 0.0f;   // parity 1
    float* c = &g_c[0][0][0];
    c[i] = 0.0f;
}

// ---------------------------------------------------------------------------
// Phase 1: embedding lookup + input-gate GEMM
// xg[d][t][b][n] = sum_k emb[idx[b,t]][k] * Wih_d[n][k] + bih_d[n] + bhh_d[n]
// block: 256 threads, 16 (b,t) pairs; each thread owns 4 output columns
// ---------------------------------------------------------------------------
__global__ void __launch_bounds__(256) embed_gemm(
    const int*   __restrict__ idx,
    const float* __restrict__ emb,
    const float* __restrict__ Wih_f, const float* __restrict__ bih_f, const float* __restrict__ bhh_f,
    const float* __restrict__ Wih_b, const float* __restrict__ bih_b, const float* __restrict__ bhh_b)
{
    __shared__ float xs[16][DD];
    const int bt0 = blockIdx.x * 16;
    const int tid = threadIdx.x;

    for (int i = tid; i < 16 * DD; i += 256) {
        int li = i / DD;
        int k  = i - li * DD;
        int bt = bt0 + li;
        int b  = bt >> 9;          // T = 512
        int t  = bt & 511;
        int id = idx[b * TT + t];
        xs[li][k] = emb[id * DD + k];
    }
    __syncthreads();

    #pragma unroll 1
    for (int gph = 0; gph < 4; ++gph) {
        int col = tid + gph * 256;          // 0..1023
        int dir = col >> 9;
        int n   = col & 511;
        const float* wr = (dir ? Wih_b : Wih_f) + n * DD;
        float bias = dir ? (bih_b[n] + bhh_b[n]) : (bih_f[n] + bhh_f[n]);

        float w[DD];
        #pragma unroll
        for (int k = 0; k < DD; ++k) w[k] = wr[k];

        #pragma unroll 1
        for (int li = 0; li < 16; ++li) {
            float acc = bias;
            #pragma unroll
            for (int k = 0; k < DD; ++k) acc = fmaf(w[k], xs[li][k], acc);
            int bt = bt0 + li;
            int b  = bt >> 9;
            int t  = bt & 511;
            g_xg[dir][t][b][n] = acc;
        }
    }
}

// ---------------------------------------------------------------------------
// Phase 2: one LSTM time step (both directions via blockIdx.z)
// grid (8 k-slices, 8 b-tiles, 2 dirs) x 512 threads
// Block owns batch tile of 32, k-slice of 16 => all 4 gate rows for its k's.
// h double-buffered across step launches; c and out are block-exclusive.
// ---------------------------------------------------------------------------
__global__ void __launch_bounds__(512) lstm_step(
    const float* __restrict__ Whh_f, const float* __restrict__ Whh_b,
    const float* __restrict__ masks, float* __restrict__ out, int s)
{
    __shared__ float smw[8192];   // weights, transposed: smw4[c*64 + row_local], 32 KB
    __shared__ float smh[4096];   // h tile [32][128]; reused as gate-exchange [32][64]

    const int tid = threadIdx.x;
    const int d   = blockIdx.z;
    const int ks0 = blockIdx.x * 16;
    const int bb0 = blockIdx.y * 32;
    const int t   = d ? (TT - 1 - s) : s;

    const float* whh = d ? Whh_b : Whh_f;

    // stage weights transposed into smem: 64 rows x 128 k (as 32 float4 chunks)
    float4* smw4 = (float4*)smw;
    const float4* whh4 = (const float4*)whh;
    for (int v = tid; v < 2048; v += 512) {
        int rl   = v >> 5;               // 0..63
        int c    = v & 31;               // k-chunk
        int gate = rl >> 4;
        int kk   = rl & 15;
        int gr   = gate * 128 + ks0 + kk;
        smw4[c * 64 + rl] = whh4[gr * 32 + c];
    }
    // stage previous h tile: 32 batches x 128 k
    float4* smh4 = (float4*)smh;
    const float4* hin4 = (const float4*)&g_h[s & 1][d][bb0][0];
    for (int v = tid; v < 1024; v += 512) {
        smh4[v] = hin4[v];
    }
    __syncthreads();

    // ---- gate preactivations: each thread -> 1 gate row x 4 batches ----
    const int j  = tid & 63;            // gate*16 + kk
    const int bg = tid >> 6;            // 0..7
    const int bl = bg * 4;              // local batch base
    const int gate = j >> 4;
    const int kk   = j & 15;
    const int r    = gate * 128 + ks0 + kk;

    const float* xg = &g_xg[d][t][0][0];
    float acc0 = xg[(bb0 + bl + 0) * G4 + r];
    float acc1 = xg[(bb0 + bl + 1) * G4 + r];
    float acc2 = xg[(bb0 + bl + 2) * G4 + r];
    float acc3 = xg[(bb0 + bl + 3) * G4 + r];

    #pragma unroll 8
    for (int c = 0; c < 32; ++c) {
        float4 w  = smw4[c * 64 + j];
        float4 h0 = smh4[(bl + 0) * 32 + c];
        float4 h1 = smh4[(bl + 1) * 32 + c];
        float4 h2 = smh4[(bl + 2) * 32 + c];
        float4 h3 = smh4[(bl + 3) * 32 + c];
        acc0 = fmaf(w.x, h0.x, acc0); acc0 = fmaf(w.y, h0.y, acc0);
        acc0 = fmaf(w.z, h0.z, acc0); acc0 = fmaf(w.w, h0.w, acc0);
        acc1 = fmaf(w.x, h1.x, acc1); acc1 = fmaf(w.y, h1.y, acc1);
        acc1 = fmaf(w.z, h1.z, acc1); acc1 = fmaf(w.w, h1.w, acc1);
        acc2 = fmaf(w.x, h2.x, acc2); acc2 = fmaf(w.y, h2.y, acc2);
        acc2 = fmaf(w.z, h2.z, acc2); acc2 = fmaf(w.w, h2.w, acc2);
        acc3 = fmaf(w.x, h3.x, acc3); acc3 = fmaf(w.y, h3.y, acc3);
        acc3 = fmaf(w.z, h3.z, acc3); acc3 = fmaf(w.w, h3.w, acc3);
    }
    __syncthreads();   // done reading h region; reuse as gate-exchange

    smh[(bl + 0) * 64 + j] = acc0;
    smh[(bl + 1) * 64 + j] = acc1;
    smh[(bl + 2) * 64 + j] = acc2;
    smh[(bl + 3) * 64 + j] = acc3;
    __syncthreads();

    // ---- c/h update + running masked max: each thread -> one (b, k) ----
    const int kk2 = tid & 15;
    const int b2  = tid >> 4;           // 0..31
    float gi = smh[b2 * 64 +  0 + kk2];
    float gf = smh[b2 * 64 + 16 + kk2];
    float gg = smh[b2 * 64 + 32 + kk2];
    float go = smh[b2 * 64 + 48 + kk2];

    const int b = bb0 + b2;
    const int k = ks0 + kk2;

    float cp = g_c[d][b][k];
    float cn = sigf(gf) * cp + sigf(gi) * tanh_fast(gg);
    float hn = sigf(go) * tanh_fast(cn);
    g_c[d][b][k] = cn;
    g_h[(s + 1) & 1][d][b][k] = hn;

    float m   = masks[b * TT + t];
    float val = hn - (1.0f - m) * 1e8f;
    float* op = out + b * HID + d * HH + k;
    float old = *op;
    *op = fmaxf(old, val);
}

// ---------------------------------------------------------------------------
extern "C" void kernel_launch(void* const* d_in, const int* in_sizes, int n_in,
                              void* d_out, int out_size)
{
    (void)in_sizes; (void)n_in; (void)out_size;
    const int*   idx   = (const int*)  d_in[0];
    const float* masks = (const float*)d_in[1];
    const float* emb   = (const float*)d_in[2];
    const float* Wih_f = (const float*)d_in[3];
    const float* Whh_f = (const float*)d_in[4];
    const float* bih_f = (const float*)d_in[5];
    const float* bhh_f = (const float*)d_in[6];
    const float* Wih_b = (const float*)d_in[7];
    const float* Whh_b = (const float*)d_in[8];
    const float* bih_b = (const float*)d_in[9];
    const float* bhh_b = (const float*)d_in[10];
    float* out = (float*)d_out;

    init_kernel<<<256, 256>>>(out);
    embed_gemm<<<(BB * TT) / 16, 256>>>(idx, emb, Wih_f, bih_f, bhh_f,
                                        Wih_b, bih_b, bhh_b);
    dim3 sg(8, 8, 2);
    for (int s = 0; s < TT; ++s)
        lstm_step<<<sg, 512>>>(Whh_f, Whh_b, masks, out, s);
}

// round 3
// speedup vs baseline: 1.2561x; 1.2561x over previous
#include <cuda_runtime.h>

#define BB 256
#define TT 512
#define DD 50
#define HH 128
#define G4 512
#define HID 256

typedef unsigned long long ull;

// ---- device scratch (no allocations allowed) ----
__device__ float    g_xgT[2][TT][G4][BB];       // input-gate preactivations, transposed [d][t][row][b]
__device__ float    g_hbuf[2][2][8][128][32];   // [parity][dir][btile][k][b]
__device__ unsigned g_cnt[16 * 32];             // 16 group barrier counters, 128B apart

__device__ __forceinline__ float sigf(float x)   { return 1.0f / (1.0f + __expf(-x)); }
__device__ __forceinline__ float tanhf_(float x) { return 2.0f / (1.0f + __expf(-2.0f * x)) - 1.0f; }

__device__ __forceinline__ ull pack2(float a, float b) {
    ull r; asm("mov.b64 %0,{%1,%2};" : "=l"(r) : "f"(a), "f"(b)); return r;
}
__device__ __forceinline__ void unpack2(ull v, float& a, float& b) {
    asm("mov.b64 {%0,%1},%2;" : "=f"(a), "=f"(b) : "l"(v));
}
__device__ __forceinline__ void fma2(ull a, ull b, ull& c) {
    asm("fma.rn.f32x2 %0,%1,%2,%0;" : "+l"(c) : "l"(a), "l"(b));
}

// ---------------------------------------------------------------------------
// Reset barrier counters (runs first every graph replay -> clean epoch)
// ---------------------------------------------------------------------------
__global__ void reset_kernel() {
    if (threadIdx.x < 16) g_cnt[threadIdx.x * 32] = 0u;
}

// ---------------------------------------------------------------------------
// Embedding lookup + input-gate GEMM -> transposed xg
// grid (8 btiles, 512 t) x 256 threads; f32x2 packed math
// xgT[d][t][n][b] = sum_k emb[idx[b,t]][k] * Wih_d[n][k] + bih_d[n] + bhh_d[n]
// ---------------------------------------------------------------------------
__global__ void __launch_bounds__(256) embed_gemm(
    const int*   __restrict__ idx,
    const float* __restrict__ emb,
    const float* __restrict__ Wih_f, const float* __restrict__ bih_f, const float* __restrict__ bhh_f,
    const float* __restrict__ Wih_b, const float* __restrict__ bih_b, const float* __restrict__ bhh_b)
{
    __shared__ __align__(16) float xsA[16 * DD * 2];  // batch-pair-major: [(b>>1)][k][b&1]
    const int tid = threadIdx.x;
    const int b0  = blockIdx.x * 32;
    const int t   = blockIdx.y;

    for (int i = tid; i < 32 * DD; i += 256) {
        int b = i / DD, k = i - b * DD;
        int id = idx[(b0 + b) * TT + t];
        xsA[(b >> 1) * (2 * DD) + k * 2 + (b & 1)] = emb[id * DD + k];
    }
    __syncthreads();

    #pragma unroll 1
    for (int g = 0; g < 4; ++g) {
        int col = tid + g * 256;        // 0..1023
        int dir = col >> 9;
        int n   = col & 511;
        const float* W = dir ? Wih_b : Wih_f;
        float bias = dir ? (bih_b[n] + bhh_b[n]) : (bih_f[n] + bhh_f[n]);

        float w[DD];
        #pragma unroll
        for (int k = 0; k < DD; ++k) w[k] = W[n * DD + k];

        ull acc[16];
        ull bp = pack2(bias, bias);
        #pragma unroll
        for (int p = 0; p < 16; ++p) acc[p] = bp;

        #pragma unroll 2
        for (int k = 0; k < DD; ++k) {
            ull w2 = pack2(w[k], w[k]);
            #pragma unroll
            for (int p = 0; p < 16; ++p) {
                ull x = *(const ull*)&xsA[p * (2 * DD) + k * 2];   // broadcast LDS.64
                fma2(x, w2, acc[p]);
            }
        }

        float* dst = &g_xgT[dir][t][n][b0];
        #pragma unroll
        for (int p = 0; p < 16; ++p) {
            float a, b; unpack2(acc[p], a, b);
            *(float2*)&dst[2 * p] = make_float2(a, b);
        }
    }
}

// ---------------------------------------------------------------------------
// Persistent bidirectional LSTM recurrence + masked running max.
// grid (8 k-slices, 8 b-tiles, 2 dirs) = 128 blocks x 256 threads, all resident.
// Block tile: 32 batches x 64 gate rows. Warp = 32 batches x 8 rows (4 f32x2 accs).
// Weights cached in smem for all 512 steps; h via double-buffered global + group barrier.
// ---------------------------------------------------------------------------
__global__ void __launch_bounds__(256, 1) lstm_persist(
    const float* __restrict__ Whh_f, const float* __restrict__ Whh_b,
    const float* __restrict__ masks, float* __restrict__ out)
{
    __shared__ __align__(16) ull   wq[8 * 128 * 4];  // 32KB: [warp][k][pair] of row-pairs
    __shared__ __align__(16) float hT[4096];         // 16KB: h tile [k][b]; reused for gates [row][b]

    const int tid  = threadIdx.x;
    const int ks   = blockIdx.x;         // k-slice 0..7
    const int bt   = blockIdx.y;         // batch tile 0..7
    const int d    = blockIdx.z;         // direction
    const int ks0  = ks * 16;
    const int bb0  = bt * 32;
    const int warp = tid >> 5;
    const int lane = tid & 31;
    const int grp  = d * 8 + bt;

    const float* Whh = d ? Whh_b : Whh_f;

    // stage weights once: wq[w][k][j] packs local rows (8w+2j, 8w+2j+1)
    for (int i = tid; i < 8192; i += 256) {
        int rl = i & 63, k = i >> 6;
        int g = rl >> 4, kk = rl & 15;
        float v = Whh[(g * 128 + ks0 + kk) * 128 + k];
        int w_ = rl >> 3, j = (rl & 7) >> 1, e = rl & 1;
        ((float*)wq)[((w_ * 128 + k) * 4 + j) * 2 + e] = v;
    }

    // update-phase mapping: thread -> batch ub, k-pair 2*ukh,2*ukh+1
    const int ub  = tid & 31;
    const int ukh = tid >> 5;
    float c0 = 0.f, c1 = 0.f;
    float m0 = -3.0e38f, m1 = -3.0e38f;

    // prefetch xg accumulator-inits for step 0
    float xn[8];
    {
        int t0 = d ? (TT - 1) : 0;
        #pragma unroll
        for (int i = 0; i < 8; ++i) {
            int rl = 8 * warp + i;
            int g = rl >> 4, kk = rl & 15;
            xn[i] = __ldg(&g_xgT[d][t0][g * 128 + ks0 + kk][bb0 + lane]);
        }
    }
    __syncthreads();

    for (int s = 0; s < TT; ++s) {
        const int t = d ? (TT - 1 - s) : s;

        // ---- stage h_{s} into smem (L2-coherent loads) ----
        if (s == 0) {
            for (int i = tid; i < 4096; i += 256) hT[i] = 0.f;
        } else {
            const float4* src = (const float4*)&g_hbuf[s & 1][d][bt][0][0];
            float4* dst = (float4*)hT;
            #pragma unroll
            for (int q = 0; q < 4; ++q) dst[tid + q * 256] = __ldcg(&src[tid + q * 256]);
        }
        __syncthreads();

        // ---- gate preactivations: 8 rows x 32 batches per warp, f32x2 ----
        ull acc0 = pack2(xn[0], xn[1]);
        ull acc1 = pack2(xn[2], xn[3]);
        ull acc2 = pack2(xn[4], xn[5]);
        ull acc3 = pack2(xn[6], xn[7]);
        const ull* wr = &wq[warp * 128 * 4];
        #pragma unroll 4
        for (int k = 0; k < 128; ++k) {
            float h = hT[k * 32 + lane];                         // conflict-free LDS.32
            ull h2 = pack2(h, h);
            ulonglong2 wa = *(const ulonglong2*)&wr[k * 4 + 0];  // broadcast LDS.128
            ulonglong2 wb = *(const ulonglong2*)&wr[k * 4 + 2];
            fma2(h2, wa.x, acc0);
            fma2(h2, wa.y, acc1);
            fma2(h2, wb.x, acc2);
            fma2(h2, wb.y, acc3);
        }
        __syncthreads();   // done reading hT; reuse as gate buffer

        {
            float a, b;
            unpack2(acc0, a, b); hT[(8 * warp + 0) * 32 + lane] = a; hT[(8 * warp + 1) * 32 + lane] = b;
            unpack2(acc1, a, b); hT[(8 * warp + 2) * 32 + lane] = a; hT[(8 * warp + 3) * 32 + lane] = b;
            unpack2(acc2, a, b); hT[(8 * warp + 4) * 32 + lane] = a; hT[(8 * warp + 5) * 32 + lane] = b;
            unpack2(acc3, a, b); hT[(8 * warp + 6) * 32 + lane] = a; hT[(8 * warp + 7) * 32 + lane] = b;
        }
        __syncthreads();

        // ---- c/h update + running masked max (rows: gate*16+kk) ----
        {
            float m   = masks[(bb0 + ub) * TT + t];
            float pen = (1.0f - m) * 1e8f;

            int kk = 2 * ukh;
            float gi = hT[(0  + kk) * 32 + ub];
            float gf = hT[(16 + kk) * 32 + ub];
            float gg = hT[(32 + kk) * 32 + ub];
            float go = hT[(48 + kk) * 32 + ub];
            c0 = sigf(gf) * c0 + sigf(gi) * tanhf_(gg);
            float hv = sigf(go) * tanhf_(c0);
            m0 = fmaxf(m0, hv - pen);
            __stcg(&g_hbuf[(s + 1) & 1][d][bt][ks0 + kk][ub], hv);

            kk = 2 * ukh + 1;
            gi = hT[(0  + kk) * 32 + ub];
            gf = hT[(16 + kk) * 32 + ub];
            gg = hT[(32 + kk) * 32 + ub];
            go = hT[(48 + kk) * 32 + ub];
            c1 = sigf(gf) * c1 + sigf(gi) * tanhf_(gg);
            hv = sigf(go) * tanhf_(c1);
            m1 = fmaxf(m1, hv - pen);
            __stcg(&g_hbuf[(s + 1) & 1][d][bt][ks0 + kk][ub], hv);
        }

        if (s < TT - 1) {
            // prefetch next step's xg (DRAM latency hides behind the barrier)
            int t2 = d ? (TT - 2 - s) : (s + 1);
            #pragma unroll
            for (int i = 0; i < 8; ++i) {
                int rl = 8 * warp + i;
                int g = rl >> 4, kk = rl & 15;
                xn[i] = __ldg(&g_xgT[d][t2][g * 128 + ks0 + kk][bb0 + lane]);
            }
            // ---- group barrier: 8 k-slice blocks of (d, bt) ----
            __threadfence();
            __syncthreads();
            if (tid == 0) {
                atomicAdd(&g_cnt[grp * 32], 1u);
                unsigned tgt = 8u * (unsigned)(s + 1);
                while (*(volatile unsigned*)&g_cnt[grp * 32] < tgt) { __nanosleep(32); }
                __threadfence();
            }
            __syncthreads();
        }
    }

    // final output (each thread owns exactly 2 of the 65536 outputs)
    out[(bb0 + ub) * HID + d * HH + ks0 + 2 * ukh]     = m0;
    out[(bb0 + ub) * HID + d * HH + ks0 + 2 * ukh + 1] = m1;
}

// ---------------------------------------------------------------------------
extern "C" void kernel_launch(void* const* d_in, const int* in_sizes, int n_in,
                              void* d_out, int out_size)
{
    (void)in_sizes; (void)n_in; (void)out_size;
    const int*   idx   = (const int*)  d_in[0];
    const float* masks = (const float*)d_in[1];
    const float* emb   = (const float*)d_in[2];
    const float* Wih_f = (const float*)d_in[3];
    const float* Whh_f = (const float*)d_in[4];
    const float* bih_f = (const float*)d_in[5];
    const float* bhh_f = (const float*)d_in[6];
    const float* Wih_b = (const float*)d_in[7];
    const float* Whh_b = (const float*)d_in[8];
    const float* bih_b = (const float*)d_in[9];
    const float* bhh_b = (const float*)d_in[10];
    float* out = (float*)d_out;

    reset_kernel<<<1, 32>>>();
    embed_gemm<<<dim3(8, TT), 256>>>(idx, emb, Wih_f, bih_f, bhh_f,
                                     Wih_b, bih_b, bhh_b);
    lstm_persist<<<dim3(8, 8, 2), 256>>>(Whh_f, Whh_b, masks, out);
}